// round 6
// baseline (speedup 1.0000x reference)
#include <cuda_runtime.h>
#include <cstdint>

typedef unsigned long long ull;

constexpr int Bn = 128;
constexpr int Tn = 1024;
constexpr int In = 256;
constexpr int Hn = 512;

// rnn smem layout (bytes)
constexpr int WS_BYTES  = 16 * 512 * 16;          // Wh smem half: [16][512] float4 = 131072
constexpr int HP_PAIR   = 520;                    // padded ull per (buf,pair): 4x(128+2)=520
constexpr int HP_BYTES  = 2 * 2 * HP_PAIR * 8;    // 16640
constexpr int MB_OFF    = WS_BYTES + HP_BYTES;    // mbar[2]
constexpr int SMEM_RNN  = MB_OFF + 16;

__device__ __forceinline__ ull pack2f(float x, float y) {
    ull r; asm("mov.b64 %0, {%1, %2};" : "=l"(r) : "f"(x), "f"(y)); return r;
}
__device__ __forceinline__ float2 unpack2f(ull v) {
    float2 r; asm("mov.b64 {%0, %1}, %2;" : "=f"(r.x), "=f"(r.y) : "l"(v)); return r;
}
__device__ __forceinline__ ull splat2f(float x) {
    ull r; asm("mov.b64 %0, {%1, %1};" : "=l"(r) : "f"(x)); return r;
}
__device__ __forceinline__ void ffma2(ull& a, ull x, ull y) {
    asm("fma.rn.f32x2 %0, %1, %2, %0;" : "+l"(a) : "l"(x), "l"(y));
}
__device__ __forceinline__ float sigmoidf_fast(float z) {
    return __fdividef(1.0f, 1.0f + __expf(-z));
}
__device__ __forceinline__ uint32_t smem_u32(const void* p) {
    return (uint32_t)__cvta_generic_to_shared(p);
}

// ---------------------------------------------------------------------------
// Kernel 1: igates = x @ Wi^T + bi  (f32x2 version, measured 777us)
// ---------------------------------------------------------------------------
__global__ __launch_bounds__(256) void igates_kernel(
    const float* __restrict__ X,
    const float* __restrict__ Wi,
    const float* __restrict__ bi,
    float* __restrict__ out)
{
    __shared__ __align__(16) float Xs[32][68];   // [k][m]
    __shared__ __align__(16) float Ws[32][68];   // [k][n]

    const int tid = threadIdx.x;
    const int tx = tid & 15;
    const int ty = tid >> 4;
    const int m0 = blockIdx.y * 64;
    const int n0 = blockIdx.x * 64;

    ull acc[4][2] = {};

    for (int k0 = 0; k0 < In; k0 += 32) {
        #pragma unroll
        for (int hh = 0; hh < 2; hh++) {
            int idx = tid + 256 * hh;
            int r   = idx >> 3;
            int c4  = idx & 7;
            float4 v = *(const float4*)(X + (size_t)(m0 + r) * In + k0 + c4 * 4);
            Xs[c4*4+0][r] = v.x; Xs[c4*4+1][r] = v.y;
            Xs[c4*4+2][r] = v.z; Xs[c4*4+3][r] = v.w;
            float4 w = *(const float4*)(Wi + (size_t)(n0 + r) * In + k0 + c4 * 4);
            Ws[c4*4+0][r] = w.x; Ws[c4*4+1][r] = w.y;
            Ws[c4*4+2][r] = w.z; Ws[c4*4+3][r] = w.w;
        }
        __syncthreads();

        #pragma unroll
        for (int k = 0; k < 32; k++) {
            float4 a4 = *(const float4*)(&Xs[k][ty * 4]);
            const ull* b2 = (const ull*)(&Ws[k][tx * 4]);
            ull bp0 = b2[0], bp1 = b2[1];
            ull s0 = splat2f(a4.x), s1 = splat2f(a4.y),
                s2 = splat2f(a4.z), s3 = splat2f(a4.w);
            ffma2(acc[0][0], s0, bp0); ffma2(acc[0][1], s0, bp1);
            ffma2(acc[1][0], s1, bp0); ffma2(acc[1][1], s1, bp1);
            ffma2(acc[2][0], s2, bp0); ffma2(acc[2][1], s2, bp1);
            ffma2(acc[3][0], s3, bp0); ffma2(acc[3][1], s3, bp1);
        }
        __syncthreads();
    }

    float4 bv = *(const float4*)(bi + n0 + tx * 4);
    #pragma unroll
    for (int i = 0; i < 4; i++) {
        float2 lo = unpack2f(acc[i][0]);
        float2 hi = unpack2f(acc[i][1]);
        float4 o = make_float4(lo.x + bv.x, lo.y + bv.y, hi.x + bv.z, hi.y + bv.w);
        *(float4*)(out + (size_t)(m0 + ty*4 + i) * Hn + n0 + tx * 4) = o;
    }
}

// ---------------------------------------------------------------------------
// Kernel 2: recurrence, 32 clusters x 4 CTAs, 512 threads/CTA.
//   Thread = (column jj 0..127, k-quarter rq 0..3). Per thread: 128 Wh
//   weights (64 regs + 64 smem), 256 FFMA2/step. k-reduction: shfl.xor 1,2
//   across the 4 rq lanes. h in smem: 2 row-pairs x 512 packed ull, double
//   buffered, 130-ull quarter stride (conflict-free 4-address LDS.128).
//   Exchange: st.shared::cluster push to 4 CTAs + mbarrier (count 64).
// ---------------------------------------------------------------------------
__global__ __launch_bounds__(512, 1) __cluster_dims__(4, 1, 1)
void rnn_kernel(
    float* __restrict__ out,
    const float* __restrict__ hidden,
    const float* __restrict__ Wh,
    const float* __restrict__ bh)
{
    extern __shared__ char sm[];
    float4* Wsm   = (float4*)sm;                 // [16][512]
    ull*    hpb   = (ull*)(sm + WS_BYTES);       // [2 buf][2 pair][520]
    ull*    mbar  = (ull*)(sm + MB_OFF);         // [2]

    const int tid  = threadIdx.x;
    const int lane = tid & 31;
    const int warp = tid >> 5;                   // 0..15
    const int jj   = (warp << 3) | (lane >> 2);  // 0..127 column in slice
    const int rq   = lane & 3;                   // k-quarter (0..3)
    const int pr   = rq & 1;                     // epilogue row-pair (rq<2 active)
    uint32_t crank; asm("mov.u32 %0, %%cluster_ctarank;" : "=r"(crank));
    const int g    = blockIdx.x >> 2;
    const int j    = (int)crank * 128 + jj;      // global column
    const float bhj = bh[j];
    const int b0   = 4 * g + 2 * pr;             // epilogue rows (b0, b0+1)
    const int jidx = j + ((j >> 7) << 1);        // padded column index

    float* __restrict__ hl = out + (size_t)Bn * Tn * Hn;

    // ---- Wh slice: k in [128*rq, 128*rq+128); first 64 -> regs, rest -> smem
    float4 W4[16];
    {
        const float4* wp = (const float4*)(Wh + (size_t)j * Hn + 128 * rq);
        #pragma unroll
        for (int u = 0; u < 16; u++) W4[u] = wp[u];
        const float4* wq = (const float4*)(Wh + (size_t)j * Hn + 128 * rq + 64);
        #pragma unroll
        for (int u = 0; u < 16; u++) Wsm[u * 512 + tid] = wq[u];
    }

    // ---- mbarrier init (count = 64 warp-arrivals: 16 warps x 4 CTAs) ----
    if (tid == 0) {
        uint32_t m0 = smem_u32(&mbar[0]), m1 = smem_u32(&mbar[1]);
        asm volatile("mbarrier.init.shared.b64 [%0], %1;" :: "r"(m0), "r"(64u) : "memory");
        asm volatile("mbarrier.init.shared.b64 [%0], %1;" :: "r"(m1), "r"(64u) : "memory");
    }

    // ---- stage initial hidden into hp buf 0 ----
    for (int i = tid; i < 1024; i += 512) {
        int pair = i >> 9, col = i & 511;
        int idx  = col + ((col >> 7) << 1);
        hpb[pair * HP_PAIR + idx] =
            pack2f(hidden[(4 * g + 2 * pair) * Hn + col],
                   hidden[(4 * g + 2 * pair + 1) * Hn + col]);
    }
    __syncthreads();

    // cluster-wide: mbar init + staging complete before any remote store/arrive
    asm volatile("barrier.cluster.arrive.aligned;" ::: "memory");
    asm volatile("barrier.cluster.wait.aligned;"   ::: "memory");

    // ---- precompute remote addresses ----
    uint32_t hp_u32 = smem_u32(hpb);
    uint32_t mb_u32 = smem_u32(mbar);
    uint32_t rhp[4], rmb[4];
    #pragma unroll
    for (int r = 0; r < 4; r++) {
        asm("mapa.shared::cluster.u32 %0, %1, %2;" : "=r"(rhp[r]) : "r"(hp_u32), "r"(r));
        asm("mapa.shared::cluster.u32 %0, %1, %2;" : "=r"(rmb[r]) : "r"(mb_u32), "r"(r));
    }
    const uint32_t poff = (uint32_t)(pr * HP_PAIR + jidx) * 8u;

    const size_t orow0 = (size_t)b0       * (Tn * Hn);
    const size_t orow1 = (size_t)(b0 + 1) * (Tn * Hn);

    for (int t = 0; t < Tn; t++) {
        const int cur = t & 1;
        const int nb  = cur ^ 1;

        // igate prefetch (rows are in-bounds for all rq since pr = rq&1)
        const float ig0 = __ldcg(out + orow0 + (size_t)t * Hn + j);
        const float ig1 = __ldcg(out + orow1 + (size_t)t * Hn + j);

        if (t > 0) {
            const uint32_t maddr = smem_u32(&mbar[cur]);
            const uint32_t phase = (uint32_t)((t - 1) >> 1) & 1u;
            uint32_t done;
            do {
                asm volatile(
                    "{\n\t.reg .pred p;\n\t"
                    "mbarrier.try_wait.parity.acquire.cluster.shared::cta.b64 p, [%1], %2, 0x989680;\n\t"
                    "selp.b32 %0, 1, 0, p;\n\t}"
                    : "=r"(done) : "r"(maddr), "r"(phase) : "memory");
            } while (!done);
        }

        // ---- compute: 2 row-pairs over this thread's 128-k quarter ----
        const ull* hp0 = hpb + cur * (2 * HP_PAIR) + 0 * HP_PAIR + 130 * rq;
        const ull* hp1 = hpb + cur * (2 * HP_PAIR) + 1 * HP_PAIR + 130 * rq;
        ull a00 = 0, a01 = 0, a10 = 0, a11 = 0;
        #pragma unroll
        for (int u = 0; u < 16; u++) {
            float4 w = W4[u];
            ull wx = splat2f(w.x), wy = splat2f(w.y),
                wz = splat2f(w.z), ww = splat2f(w.w);
            ulonglong2 h0a = *(const ulonglong2*)(hp0 + 4*u);
            ulonglong2 h0b = *(const ulonglong2*)(hp0 + 4*u + 2);
            ffma2(a00, wx, h0a.x); ffma2(a01, wy, h0a.y);
            ffma2(a00, wz, h0b.x); ffma2(a01, ww, h0b.y);
            ulonglong2 h1a = *(const ulonglong2*)(hp1 + 4*u);
            ulonglong2 h1b = *(const ulonglong2*)(hp1 + 4*u + 2);
            ffma2(a10, wx, h1a.x); ffma2(a11, wy, h1a.y);
            ffma2(a10, wz, h1b.x); ffma2(a11, ww, h1b.y);
        }
        #pragma unroll
        for (int u = 0; u < 16; u++) {
            float4 w = Wsm[u * 512 + tid];
            ull wx = splat2f(w.x), wy = splat2f(w.y),
                wz = splat2f(w.z), ww = splat2f(w.w);
            ulonglong2 h0a = *(const ulonglong2*)(hp0 + 64 + 4*u);
            ulonglong2 h0b = *(const ulonglong2*)(hp0 + 64 + 4*u + 2);
            ffma2(a00, wx, h0a.x); ffma2(a01, wy, h0a.y);
            ffma2(a00, wz, h0b.x); ffma2(a01, ww, h0b.y);
            ulonglong2 h1a = *(const ulonglong2*)(hp1 + 64 + 4*u);
            ulonglong2 h1b = *(const ulonglong2*)(hp1 + 64 + 4*u + 2);
            ffma2(a10, wx, h1a.x); ffma2(a11, wy, h1a.y);
            ffma2(a10, wz, h1b.x); ffma2(a11, ww, h1b.y);
        }

        // ---- k-quarter reduction across the 4 rq lanes (xor 1, xor 2) ----
        float2 s0 = unpack2f(a00), s0b = unpack2f(a01);
        float2 s1 = unpack2f(a10), s1b = unpack2f(a11);
        float p0x = s0.x + s0b.x, p0y = s0.y + s0b.y;
        float p1x = s1.x + s1b.x, p1y = s1.y + s1b.y;
        p0x += __shfl_xor_sync(0xffffffffu, p0x, 1);
        p0y += __shfl_xor_sync(0xffffffffu, p0y, 1);
        p1x += __shfl_xor_sync(0xffffffffu, p1x, 1);
        p1y += __shfl_xor_sync(0xffffffffu, p1y, 1);
        p0x += __shfl_xor_sync(0xffffffffu, p0x, 2);
        p0y += __shfl_xor_sync(0xffffffffu, p0y, 2);
        p1x += __shfl_xor_sync(0xffffffffu, p1x, 2);
        p1y += __shfl_xor_sync(0xffffffffu, p1y, 2);

        // ---- epilogue (lanes rq<2 only): bias + ig + sigmoid, stores, push ----
        if (rq < 2) {
            const float zx = (pr ? p1x : p0x) + ig0 + bhj;
            const float zy = (pr ? p1y : p0y) + ig1 + bhj;
            float h0v = sigmoidf_fast(zx);
            float h1v = sigmoidf_fast(zy);

            out[orow0 + (size_t)t * Hn + j] = h0v;
            out[orow1 + (size_t)t * Hn + j] = h1v;
            if (t == Tn - 1) {
                hl[b0 * Hn + j]       = h0v;
                hl[(b0 + 1) * Hn + j] = h1v;
            }
            const ull v = pack2f(h0v, h1v);
            const uint32_t boff = (uint32_t)(nb * 2 * HP_PAIR) * 8u + poff;
            #pragma unroll
            for (int r = 0; r < 4; r++) {
                asm volatile("st.shared::cluster.u64 [%0], %1;"
                             :: "r"(rhp[r] + boff), "l"(v) : "memory");
            }
        }

        // ---- per-warp arrival on all 4 CTAs' mbar[nb] ----
        __syncwarp();
        if (lane == 0) {
            const uint32_t moff = (uint32_t)nb * 8u;
            #pragma unroll
            for (int r = 0; r < 4; r++) {
                asm volatile("mbarrier.arrive.release.cluster.shared::cluster.b64 _, [%0];"
                             :: "r"(rmb[r] + moff) : "memory");
            }
        }
    }

    // ---- REQUIRED: no CTA may exit while peers' DSMEM stores / mbarrier
    // arrivals targeting its SMEM are still in flight. ----
    asm volatile("barrier.cluster.arrive.aligned;" ::: "memory");
    asm volatile("barrier.cluster.wait.aligned;"   ::: "memory");
}

// ---------------------------------------------------------------------------
// Launch
// ---------------------------------------------------------------------------
extern "C" void kernel_launch(void* const* d_in, const int* in_sizes, int n_in,
                              void* d_out, int out_size)
{
    const float* x      = (const float*)d_in[0];   // [B, T, I]
    const float* hidden = (const float*)d_in[1];   // [B, H]
    const float* Wi     = (const float*)d_in[2];   // [H, I]
    const float* bi     = (const float*)d_in[3];   // [H]
    const float* Wh     = (const float*)d_in[4];   // [H, H]
    const float* bh     = (const float*)d_in[5];   // [H]
    float* out = (float*)d_out;                    // [B,T,H] then [B,H] h_last

    dim3 g1(Hn / 64, (Bn * Tn) / 64);
    igates_kernel<<<g1, 256>>>(x, Wi, bi, out);

    static bool attr_set = false;
    if (!attr_set) {
        cudaFuncSetAttribute(rnn_kernel,
                             cudaFuncAttributeMaxDynamicSharedMemorySize, SMEM_RNN);
        attr_set = true;
    }
    rnn_kernel<<<128, 512, SMEM_RNN>>>(out, hidden, Wh, bh);
}

// round 7
// speedup vs baseline: 1.4372x; 1.4372x over previous
#include <cuda_runtime.h>
#include <cstdint>

typedef unsigned long long ull;

constexpr int Bn = 128;
constexpr int Tn = 1024;
constexpr int In = 256;
constexpr int Hn = 512;

// rnn smem layout (bytes)
constexpr int WS_BYTES  = 32 * 256 * 16;          // Wh smem (col1): [32][256] float4 = 131072
constexpr int HP_PAIR   = 520;                    // padded ull per (buf,pair)
constexpr int HP_BYTES  = 2 * 2 * HP_PAIR * 8;    // 16640
constexpr int MB_OFF    = WS_BYTES + HP_BYTES;    // mbar[2]
constexpr int SMEM_RNN  = MB_OFF + 16;

__device__ __forceinline__ ull pack2f(float x, float y) {
    ull r; asm("mov.b64 %0, {%1, %2};" : "=l"(r) : "f"(x), "f"(y)); return r;
}
__device__ __forceinline__ float2 unpack2f(ull v) {
    float2 r; asm("mov.b64 {%0, %1}, %2;" : "=f"(r.x), "=f"(r.y) : "l"(v)); return r;
}
__device__ __forceinline__ ull splat2f(float x) {
    ull r; asm("mov.b64 %0, {%1, %1};" : "=l"(r) : "f"(x)); return r;
}
__device__ __forceinline__ void ffma2(ull& a, ull x, ull y) {
    asm("fma.rn.f32x2 %0, %1, %2, %0;" : "+l"(a) : "l"(x), "l"(y));
}
__device__ __forceinline__ float sigmoidf_fast(float z) {
    return __fdividef(1.0f, 1.0f + __expf(-z));
}
__device__ __forceinline__ uint32_t smem_u32(const void* p) {
    return (uint32_t)__cvta_generic_to_shared(p);
}

// ---------------------------------------------------------------------------
// Kernel 1: igates = x @ Wi^T + bi  (f32x2 version, measured 777us)
// ---------------------------------------------------------------------------
__global__ __launch_bounds__(256) void igates_kernel(
    const float* __restrict__ X,
    const float* __restrict__ Wi,
    const float* __restrict__ bi,
    float* __restrict__ out)
{
    __shared__ __align__(16) float Xs[32][68];   // [k][m]
    __shared__ __align__(16) float Ws[32][68];   // [k][n]

    const int tid = threadIdx.x;
    const int tx = tid & 15;
    const int ty = tid >> 4;
    const int m0 = blockIdx.y * 64;
    const int n0 = blockIdx.x * 64;

    ull acc[4][2] = {};

    for (int k0 = 0; k0 < In; k0 += 32) {
        #pragma unroll
        for (int hh = 0; hh < 2; hh++) {
            int idx = tid + 256 * hh;
            int r   = idx >> 3;
            int c4  = idx & 7;
            float4 v = *(const float4*)(X + (size_t)(m0 + r) * In + k0 + c4 * 4);
            Xs[c4*4+0][r] = v.x; Xs[c4*4+1][r] = v.y;
            Xs[c4*4+2][r] = v.z; Xs[c4*4+3][r] = v.w;
            float4 w = *(const float4*)(Wi + (size_t)(n0 + r) * In + k0 + c4 * 4);
            Ws[c4*4+0][r] = w.x; Ws[c4*4+1][r] = w.y;
            Ws[c4*4+2][r] = w.z; Ws[c4*4+3][r] = w.w;
        }
        __syncthreads();

        #pragma unroll
        for (int k = 0; k < 32; k++) {
            float4 a4 = *(const float4*)(&Xs[k][ty * 4]);
            const ull* b2 = (const ull*)(&Ws[k][tx * 4]);
            ull bp0 = b2[0], bp1 = b2[1];
            ull s0 = splat2f(a4.x), s1 = splat2f(a4.y),
                s2 = splat2f(a4.z), s3 = splat2f(a4.w);
            ffma2(acc[0][0], s0, bp0); ffma2(acc[0][1], s0, bp1);
            ffma2(acc[1][0], s1, bp0); ffma2(acc[1][1], s1, bp1);
            ffma2(acc[2][0], s2, bp0); ffma2(acc[2][1], s2, bp1);
            ffma2(acc[3][0], s3, bp0); ffma2(acc[3][1], s3, bp1);
        }
        __syncthreads();
    }

    float4 bv = *(const float4*)(bi + n0 + tx * 4);
    #pragma unroll
    for (int i = 0; i < 4; i++) {
        float2 lo = unpack2f(acc[i][0]);
        float2 hi = unpack2f(acc[i][1]);
        float4 o = make_float4(lo.x + bv.x, lo.y + bv.y, hi.x + bv.z, hi.y + bv.w);
        *(float4*)(out + (size_t)(m0 + ty*4 + i) * Hn + n0 + tx * 4) = o;
    }
}

// ---------------------------------------------------------------------------
// Kernel 2: recurrence, 32 clusters x 4 CTAs, 256 threads/CTA.
//   Thread = (column PAIR jj2 0..63, k-quarter rq 0..3 of 128 k).
//   Columns j0 = crank*128 + 2*jj2, j1 = j0+1. Wh[j0] quarter in registers
//   (32 float4), Wh[j1] quarter in smem. h loaded once per k, used for both
//   columns -> h-LDS traffic halved vs 1-col/thread. 512 FFMA2/thread.
//   k-reduction: shfl.xor 1,2 over the 4 rq lanes; lane rq then owns
//   (col c = rq>>1, pair pr = rq&1) -> sigmoid + 1 ull DSMEM push to 4 CTAs.
//   mbarrier count 32 (8 warps x 4 CTAs), ping-pong phases, trailing
//   cluster barrier (required: peers' DSMEM stores target our SMEM).
// ---------------------------------------------------------------------------
__global__ __launch_bounds__(256, 1) __cluster_dims__(4, 1, 1)
void rnn_kernel(
    float* __restrict__ out,
    const float* __restrict__ hidden,
    const float* __restrict__ Wh,
    const float* __restrict__ bh)
{
    extern __shared__ char sm[];
    float4* Wsm   = (float4*)sm;                 // [32][256] col1 weights
    ull*    hpb   = (ull*)(sm + WS_BYTES);       // [2 buf][2 pair][520]
    ull*    mbar  = (ull*)(sm + MB_OFF);         // [2]

    const int tid  = threadIdx.x;
    const int lane = tid & 31;
    const int warp = tid >> 5;
    const int jj2  = (warp << 3) | (lane >> 2);  // 0..63 column-pair in slice
    const int rq   = lane & 3;                   // k-quarter
    const int c    = rq >> 1;                    // epilogue column select
    const int pr   = rq & 1;                     // epilogue row-pair select
    uint32_t crank; asm("mov.u32 %0, %%cluster_ctarank;" : "=r"(crank));
    const int g    = blockIdx.x >> 2;
    const int j0   = (int)crank * 128 + (jj2 << 1);   // first column
    const int j    = j0 + c;                          // epilogue column
    const float bhj = bh[j];
    const int b0   = 4 * g + 2 * pr;             // epilogue rows (b0, b0+1)
    const int jidx = j + ((j >> 7) << 1);        // padded column index

    float* __restrict__ hl = out + (size_t)Bn * Tn * Hn;

    // ---- Wh: col0 quarter -> 128 regs; col1 quarter -> smem ----
    float4 W4[32];
    {
        const float4* wp = (const float4*)(Wh + (size_t)j0 * Hn + 128 * rq);
        #pragma unroll
        for (int u = 0; u < 32; u++) W4[u] = wp[u];
        const float4* wq = (const float4*)(Wh + (size_t)(j0 + 1) * Hn + 128 * rq);
        #pragma unroll
        for (int u = 0; u < 32; u++) Wsm[u * 256 + tid] = wq[u];
    }

    // ---- mbarrier init (count = 32: 8 warps x 4 CTAs) ----
    if (tid == 0) {
        uint32_t m0 = smem_u32(&mbar[0]), m1 = smem_u32(&mbar[1]);
        asm volatile("mbarrier.init.shared.b64 [%0], %1;" :: "r"(m0), "r"(32u) : "memory");
        asm volatile("mbarrier.init.shared.b64 [%0], %1;" :: "r"(m1), "r"(32u) : "memory");
    }

    // ---- stage initial hidden into hp buf 0 ----
    for (int i = tid; i < 1024; i += 256) {
        int pair = i >> 9, col = i & 511;
        int idx  = col + ((col >> 7) << 1);
        hpb[pair * HP_PAIR + idx] =
            pack2f(hidden[(4 * g + 2 * pair) * Hn + col],
                   hidden[(4 * g + 2 * pair + 1) * Hn + col]);
    }
    __syncthreads();

    // cluster-wide: mbar init + staging complete before any remote store/arrive
    asm volatile("barrier.cluster.arrive.aligned;" ::: "memory");
    asm volatile("barrier.cluster.wait.aligned;"   ::: "memory");

    // ---- precompute remote addresses ----
    uint32_t hp_u32 = smem_u32(hpb);
    uint32_t mb_u32 = smem_u32(mbar);
    uint32_t rhp[4], rmb[4];
    #pragma unroll
    for (int r = 0; r < 4; r++) {
        asm("mapa.shared::cluster.u32 %0, %1, %2;" : "=r"(rhp[r]) : "r"(hp_u32), "r"(r));
        asm("mapa.shared::cluster.u32 %0, %1, %2;" : "=r"(rmb[r]) : "r"(mb_u32), "r"(r));
    }
    const uint32_t poff = (uint32_t)(pr * HP_PAIR + jidx) * 8u;

    const size_t orow0 = (size_t)b0       * (Tn * Hn);
    const size_t orow1 = (size_t)(b0 + 1) * (Tn * Hn);

    for (int t = 0; t < Tn; t++) {
        const int cur = t & 1;
        const int nb  = cur ^ 1;

        // igate prefetch (independent of h)
        const float ig0 = __ldcg(out + orow0 + (size_t)t * Hn + j);
        const float ig1 = __ldcg(out + orow1 + (size_t)t * Hn + j);

        if (t > 0) {
            const uint32_t maddr = smem_u32(&mbar[cur]);
            const uint32_t phase = (uint32_t)((t - 1) >> 1) & 1u;
            uint32_t done;
            do {
                asm volatile(
                    "{\n\t.reg .pred p;\n\t"
                    "mbarrier.try_wait.parity.acquire.cluster.shared::cta.b64 p, [%1], %2, 0x989680;\n\t"
                    "selp.b32 %0, 1, 0, p;\n\t}"
                    : "=r"(done) : "r"(maddr), "r"(phase) : "memory");
            } while (!done);
        }

        // ---- compute: 2 cols x 2 row-pairs over this thread's 128-k quarter
        const ull* hp0 = hpb + cur * (2 * HP_PAIR) + 0 * HP_PAIR + 130 * rq;
        const ull* hp1 = hpb + cur * (2 * HP_PAIR) + 1 * HP_PAIR + 130 * rq;
        // acc[col][pair], 2 chains each (even/odd k)
        ull a00 = 0, a01 = 0, a02 = 0, a03 = 0;   // col0: pair0 e/o, pair1 e/o
        ull a10 = 0, a11 = 0, a12 = 0, a13 = 0;   // col1
        #pragma unroll
        for (int u = 0; u < 32; u++) {
            float4 wa = W4[u];
            float4 wb = Wsm[u * 256 + tid];
            ulonglong2 h0a = *(const ulonglong2*)(hp0 + 4*u);
            ulonglong2 h0b = *(const ulonglong2*)(hp0 + 4*u + 2);
            ulonglong2 h1a = *(const ulonglong2*)(hp1 + 4*u);
            ulonglong2 h1b = *(const ulonglong2*)(hp1 + 4*u + 2);
            ull ax = splat2f(wa.x), ay = splat2f(wa.y),
                az = splat2f(wa.z), aw = splat2f(wa.w);
            ffma2(a00, ax, h0a.x); ffma2(a01, ay, h0a.y);
            ffma2(a00, az, h0b.x); ffma2(a01, aw, h0b.y);
            ffma2(a02, ax, h1a.x); ffma2(a03, ay, h1a.y);
            ffma2(a02, az, h1b.x); ffma2(a03, aw, h1b.y);
            ull bx = splat2f(wb.x), by = splat2f(wb.y),
                bz = splat2f(wb.z), bw = splat2f(wb.w);
            ffma2(a10, bx, h0a.x); ffma2(a11, by, h0a.y);
            ffma2(a10, bz, h0b.x); ffma2(a11, bw, h0b.y);
            ffma2(a12, bx, h1a.x); ffma2(a13, by, h1a.y);
            ffma2(a12, bz, h1b.x); ffma2(a13, bw, h1b.y);
        }

        // combine even/odd chains -> P[col][pair] as float2 (rows b,b+1)
        float2 P00, P01, P10, P11;
        { float2 e = unpack2f(a00), o = unpack2f(a01); P00 = make_float2(e.x+o.x, e.y+o.y); }
        { float2 e = unpack2f(a02), o = unpack2f(a03); P01 = make_float2(e.x+o.x, e.y+o.y); }
        { float2 e = unpack2f(a10), o = unpack2f(a11); P10 = make_float2(e.x+o.x, e.y+o.y); }
        { float2 e = unpack2f(a12), o = unpack2f(a13); P11 = make_float2(e.x+o.x, e.y+o.y); }

        // ---- k-quarter reduction over the 4 rq lanes (xor 1, xor 2) ----
        #pragma unroll
        for (int mdist = 1; mdist <= 2; mdist <<= 1) {
            P00.x += __shfl_xor_sync(0xffffffffu, P00.x, mdist);
            P00.y += __shfl_xor_sync(0xffffffffu, P00.y, mdist);
            P01.x += __shfl_xor_sync(0xffffffffu, P01.x, mdist);
            P01.y += __shfl_xor_sync(0xffffffffu, P01.y, mdist);
            P10.x += __shfl_xor_sync(0xffffffffu, P10.x, mdist);
            P10.y += __shfl_xor_sync(0xffffffffu, P10.y, mdist);
            P11.x += __shfl_xor_sync(0xffffffffu, P11.x, mdist);
            P11.y += __shfl_xor_sync(0xffffffffu, P11.y, mdist);
        }

        // ---- epilogue: lane rq owns (col c, pair pr) ----
        float2 z = c ? (pr ? P11 : P10) : (pr ? P01 : P00);
        float h0v = sigmoidf_fast(z.x + ig0 + bhj);
        float h1v = sigmoidf_fast(z.y + ig1 + bhj);

        out[orow0 + (size_t)t * Hn + j] = h0v;
        out[orow1 + (size_t)t * Hn + j] = h1v;
        if (t == Tn - 1) {
            hl[b0 * Hn + j]       = h0v;
            hl[(b0 + 1) * Hn + j] = h1v;
        }
        const ull v = pack2f(h0v, h1v);
        const uint32_t boff = (uint32_t)(nb * 2 * HP_PAIR) * 8u + poff;
        #pragma unroll
        for (int r = 0; r < 4; r++) {
            asm volatile("st.shared::cluster.u64 [%0], %1;"
                         :: "r"(rhp[r] + boff), "l"(v) : "memory");
        }

        // ---- per-warp arrival on all 4 CTAs' mbar[nb] ----
        __syncwarp();
        if (lane == 0) {
            const uint32_t moff = (uint32_t)nb * 8u;
            #pragma unroll
            for (int r = 0; r < 4; r++) {
                asm volatile("mbarrier.arrive.release.cluster.shared::cluster.b64 _, [%0];"
                             :: "r"(rmb[r] + moff) : "memory");
            }
        }
    }

    // ---- REQUIRED: peers' DSMEM stores / arrivals may still target our SMEM
    asm volatile("barrier.cluster.arrive.aligned;" ::: "memory");
    asm volatile("barrier.cluster.wait.aligned;"   ::: "memory");
}

// ---------------------------------------------------------------------------
// Launch
// ---------------------------------------------------------------------------
extern "C" void kernel_launch(void* const* d_in, const int* in_sizes, int n_in,
                              void* d_out, int out_size)
{
    const float* x      = (const float*)d_in[0];   // [B, T, I]
    const float* hidden = (const float*)d_in[1];   // [B, H]
    const float* Wi     = (const float*)d_in[2];   // [H, I]
    const float* bi     = (const float*)d_in[3];   // [H]
    const float* Wh     = (const float*)d_in[4];   // [H, H]
    const float* bh     = (const float*)d_in[5];   // [H]
    float* out = (float*)d_out;                    // [B,T,H] then [B,H] h_last

    dim3 g1(Hn / 64, (Bn * Tn) / 64);
    igates_kernel<<<g1, 256>>>(x, Wi, bi, out);

    static bool attr_set = false;
    if (!attr_set) {
        cudaFuncSetAttribute(rnn_kernel,
                             cudaFuncAttributeMaxDynamicSharedMemorySize, SMEM_RNN);
        attr_set = true;
    }
    rnn_kernel<<<128, 256, SMEM_RNN>>>(out, hidden, Wh, bh);
}